// round 7
// baseline (speedup 1.0000x reference)
#include <cuda_runtime.h>
#include <cuda_fp16.h>
#include <cstdint>

// Routed capsule layer, B200 (sm_100a).
// x[64,1152,8], W[64,1152,16,8] -> v[64,64,16], 3 routing iterations.
// b_t = (sum_{tau<=t} v_tau) . u  (logits linear in history); iter-1 c == 1/64.
// u cached in fp16, layout [b][i][o][k].
// L2-residency strategy: process batches in 2 groups of 32 -> per-group u slice
// (75.5 MB) fits in L2 (~126 MB), so the two route passes read u from L2.

#define NB 64
#define NBG 32              // batches per group
#define NI 1152
#define KI 8
#define NO 64
#define KO 16

#define K1_IC 16
#define NCH1 (NI / K1_IC)   // 72 i-chunks for k_u partials
#define K2_IC 64
#define NCH2 (NI / K2_IC)   // 18 i-chunks for k_route partials

__device__ __half g_u[(size_t)NB * NI * NO * KO];        // 151 MB (75.5/group)
// chunk-major partials: [chunk][b][o][k] -> coalesced writes AND reads
__device__ float g_sp[(size_t)NCH1 * NB * NO * KO];
__device__ float g_v1[NB * NO * KO];
__device__ float g_vsum[NB * NO * KO];

// ---------------------------------------------------------------------------
// K1: u = W.x (fp16) + per-chunk partial sums (uniform-c first iteration),
// for batches [b0, b0+NBG). 8 warps (one o each); lane = ih*16 + k; W slice
// in registers. Group x tile staged once; stores gathered through smem ->
// one STG.128 per thread per b. grid = (72 i-chunks, 8 o-chunks).
// ---------------------------------------------------------------------------
__global__ void __launch_bounds__(256, 2) k_u(const float* __restrict__ x,
                                              const float* __restrict__ W,
                                              int b0) {
    __shared__ float sX[NBG * K1_IC * KI];           // 16 KB: [b][i_local][j]
    __shared__ __half sG[2][K1_IC * 8 * KO];         // 2 x 4 KB gather tiles

    const int ich = blockIdx.x, och = blockIdx.y;
    const int t = threadIdx.x;
    const int w = t >> 5;                   // local o
    const int l = t & 31;
    const int ih = l >> 4, k = l & 15;
    const int og = och * 8 + w;

    {   // stage x for the group's batches: 1024 float4, 4 per thread
        const float4* xs = (const float4*)(x + (size_t)ich * K1_IC * KI);
        float4* sx4 = (float4*)sX;
#pragma unroll
        for (int it = 0; it < 4; it++) {
            int idx = t + it * 256;
            int b = idx >> 5, r = idx & 31;
            sx4[idx] = xs[(size_t)(b0 + b) * (NI * KI / 4) + r];
        }
    }

    // register-resident W slice: 8 i x 8 j for this (og, k)
    float4 wr[16];
    {
        const float4* wp = (const float4*)(
            W + ((size_t)(og * NI + ich * K1_IC + ih * 8) * KO + k) * KI);
#pragma unroll
        for (int i = 0; i < 8; i++) {
            wr[2 * i]     = wp[i * 32];
            wr[2 * i + 1] = wp[i * 32 + 1];
        }
    }
    __syncthreads();

    const int grow = t >> 4;          // gather-store row (i_local 0..15)
    const int gcol = t & 15;          // gather-store col (16B unit)

    for (int bl = 0; bl < NBG; bl++) {
        const int b = b0 + bl;
        __half* gb = sG[bl & 1];
        float acc = 0.f;
        const float4* xb = (const float4*)(sX + bl * (K1_IC * KI) + ih * 64);
#pragma unroll
        for (int i = 0; i < 8; i++) {
            const float4 x0 = xb[2 * i];
            const float4 x1 = xb[2 * i + 1];
            float v = wr[2*i].x   * x0.x + wr[2*i].y   * x0.y
                    + wr[2*i].z   * x0.z + wr[2*i].w   * x0.w
                    + wr[2*i+1].x * x1.x + wr[2*i+1].y * x1.y
                    + wr[2*i+1].z * x1.z + wr[2*i+1].w * x1.w;
            gb[(ih * 8 + i) * (8 * KO) + w * KO + k] = __float2half(v);
            acc += v;
        }
        acc += __shfl_xor_sync(0xffffffffu, acc, 16);   // join the two i-halves
        if (l < 16)   // chunk-major partial: [ich][b][og][k] (coalesced)
            g_sp[(size_t)(ich * NB + b) * (NO * KO) + og * KO + l] = acc;
        __syncthreads();   // gather tile complete
        uint4 val = ((const uint4*)gb)[t];
        ((uint4*)(g_u + (size_t)(b * NI + ich * K1_IC + grow) * (NO * KO)
                      + och * 128))[gcol] = val;
        // next iteration writes the other sG buffer: no barrier needed here
    }
}

// ---------------------------------------------------------------------------
// transient-unpack helpers: consume packed fp16x8 without materializing floats
// ---------------------------------------------------------------------------
__device__ __forceinline__ float dot8(uint4 r, const float* v) {
    float p = 0.f; float2 f;
    f = __half22float2(*(const __half2*)&r.x); p += v[0]*f.x + v[1]*f.y;
    f = __half22float2(*(const __half2*)&r.y); p += v[2]*f.x + v[3]*f.y;
    f = __half22float2(*(const __half2*)&r.z); p += v[4]*f.x + v[5]*f.y;
    f = __half22float2(*(const __half2*)&r.w); p += v[6]*f.x + v[7]*f.y;
    return p;
}
__device__ __forceinline__ void fma8(uint4 r, float c, float* a) {
    float2 f;
    f = __half22float2(*(const __half2*)&r.x); a[0] += c*f.x; a[1] += c*f.y;
    f = __half22float2(*(const __half2*)&r.y); a[2] += c*f.x; a[3] += c*f.y;
    f = __half22float2(*(const __half2*)&r.z); a[4] += c*f.x; a[5] += c*f.y;
    f = __half22float2(*(const __half2*)&r.w); a[6] += c*f.x; a[7] += c*f.y;
}

// ---------------------------------------------------------------------------
// K2/K3: routing pass over batches [b0, b0+NBG). Warp handles one (b,i) per
// iteration: lane l owns the kh=(l&1) half (8 k's) of o in {l>>1, 16+(l>>1),
// 32+(l>>1), 48+(l>>1)}: four coalesced uint4 loads per iter (2KB/warp),
// next iteration prefetched (8 outstanding 128B loads/warp). u slice for the
// group is expected L2-resident (written by the preceding k_u launch).
// grid = (18 i-chunks, 32 b), 256 threads (8 warps x 8 i each).
// ---------------------------------------------------------------------------
__global__ void __launch_bounds__(256, 2) k_route(int use_vsum, int b0) {
    const float* __restrict__ vin = use_vsum ? g_vsum : g_v1;
    __shared__ float sRed[8 * NO * KO];     // 32 KB per-warp partials

    const int ich = blockIdx.x, b = b0 + blockIdx.y;
    const int t = threadIdx.x, w = t >> 5, l = t & 31;
    const int o0 = l >> 1, kh = l & 1;

    // v slices for this lane's 4 capsules (8 floats each)
    float v[4][8];
#pragma unroll
    for (int m = 0; m < 4; m++) {
        const float4* p = (const float4*)(vin + ((size_t)b * NO + (m * 16 + o0)) * KO + kh * 8);
        float4 a = p[0], c = p[1];
        v[m][0]=a.x; v[m][1]=a.y; v[m][2]=a.z; v[m][3]=a.w;
        v[m][4]=c.x; v[m][5]=c.y; v[m][6]=c.z; v[m][7]=c.w;
    }
    float acc[4][8];
#pragma unroll
    for (int m = 0; m < 4; m++)
#pragma unroll
        for (int q = 0; q < 8; q++) acc[m][q] = 0.f;

    // base for this warp's 8 i's; each i-row is 128 uint4
    const uint4* ub = (const uint4*)(g_u + (size_t)(b * NI + ich * K2_IC + w * 8) * (NO * KO));
    uint4 P0 = ub[l], P1 = ub[l + 32], P2 = ub[l + 64], P3 = ub[l + 96];

#pragma unroll
    for (int it = 0; it < 8; it++) {
        uint4 C0 = P0, C1 = P1, C2 = P2, C3 = P3;
        if (it < 7) {
            const uint4* un = ub + (it + 1) * 128;
            P0 = un[l]; P1 = un[l + 32]; P2 = un[l + 64]; P3 = un[l + 96];
        }
        float L[4];
        L[0] = dot8(C0, v[0]); L[1] = dot8(C1, v[1]);
        L[2] = dot8(C2, v[2]); L[3] = dot8(C3, v[3]);
#pragma unroll
        for (int m = 0; m < 4; m++)
            L[m] += __shfl_xor_sync(0xffffffffu, L[m], 1);   // full 16-k dot

        float mx = fmaxf(fmaxf(L[0], L[1]), fmaxf(L[2], L[3]));
#pragma unroll
        for (int d = 2; d <= 16; d <<= 1)
            mx = fmaxf(mx, __shfl_xor_sync(0xffffffffu, mx, d));
        float e0 = __expf(L[0] - mx), e1 = __expf(L[1] - mx);
        float e2 = __expf(L[2] - mx), e3 = __expf(L[3] - mx);
        float sm = (e0 + e1) + (e2 + e3);
#pragma unroll
        for (int d = 2; d <= 16; d <<= 1)
            sm += __shfl_xor_sync(0xffffffffu, sm, d);
        const float inv = __fdividef(1.f, sm);
        fma8(C0, e0 * inv, acc[0]); fma8(C1, e1 * inv, acc[1]);
        fma8(C2, e2 * inv, acc[2]); fma8(C3, e3 * inv, acc[3]);
    }

    // per-warp partials -> smem; element index for (m,lane) is 256*m + 8*l + q
    float4* sr4 = (float4*)sRed;
#pragma unroll
    for (int m = 0; m < 4; m++) {
        sr4[w * 256 + m * 64 + 2 * l]     = make_float4(acc[m][0], acc[m][1], acc[m][2], acc[m][3]);
        sr4[w * 256 + m * 64 + 2 * l + 1] = make_float4(acc[m][4], acc[m][5], acc[m][6], acc[m][7]);
    }
    __syncthreads();
    float4 r = sr4[t];
#pragma unroll
    for (int ww = 1; ww < 8; ww++) {
        float4 p = sr4[ww * 256 + t];
        r.x += p.x; r.y += p.y; r.z += p.z; r.w += p.w;
    }
    ((float4*)(g_sp + (size_t)(ich * NB + b) * (NO * KO)))[t] = r;   // coalesced
}

// ---------------------------------------------------------------------------
// Reduce chunk partials -> s, squash, write v, for batches [b0, b0+NBG).
// One thread per (b,o,k) element; coalesced chunk-major loads.
// mode 0: v1 = squash(s/64); mode 1: vsum = v1 + squash(s); mode 2: out.
// grid = 128 blocks (32768 threads).
// ---------------------------------------------------------------------------
__global__ void __launch_bounds__(256) k_reduce(int nch, float scale, int mode,
                                                int b0, float* __restrict__ dout) {
    const int tg = b0 * (NO * KO) + blockIdx.x * 256 + threadIdx.x;
    const float* p = g_sp + tg;
    float s = 0.f;
#pragma unroll 6
    for (int c = 0; c < nch; c++) s += p[(size_t)c * (NB * NO * KO)];
    s *= scale;
    float n2 = s * s;
#pragma unroll
    for (int d = 1; d <= 8; d <<= 1)
        n2 += __shfl_xor_sync(0xffffffffu, n2, d);   // stays within k-group
    const float scl = n2 / (1.f + n2) * rsqrtf(n2 + 1e-7f);
    const float val = s * scl;
    if (mode == 0)      g_v1[tg] = val;
    else if (mode == 1) g_vsum[tg] = val + g_v1[tg];
    else                dout[tg] = val;
}

// ---------------------------------------------------------------------------
extern "C" void kernel_launch(void* const* d_in, const int* in_sizes, int n_in,
                              void* d_out, int out_size) {
    const float* x = (const float*)d_in[0];
    const float* W = (const float*)d_in[1];
    if (in_sizes[0] != NB * NI * KI) {
        x = (const float*)d_in[1];
        W = (const float*)d_in[0];
    }
    float* out = (float*)d_out;

    for (int g = 0; g < NB / NBG; g++) {
        const int b0 = g * NBG;
        k_u<<<dim3(NCH1, NO / 8), 256>>>(x, W, b0);               // u + s1 partials
        k_reduce<<<128, 256>>>(NCH1, 1.f / 64.f, 0, b0, nullptr); // v1
        k_route<<<dim3(NCH2, NBG), 256>>>(0, b0);                 // s2
        k_reduce<<<128, 256>>>(NCH2, 1.f, 1, b0, nullptr);        // v2, vsum
        k_route<<<dim3(NCH2, NBG), 256>>>(1, b0);                 // s3
        k_reduce<<<128, 256>>>(NCH2, 1.f, 2, b0, out);            // v3 -> out
    }
}

// round 9
// speedup vs baseline: 1.1581x; 1.1581x over previous
#include <cuda_runtime.h>
#include <cuda_fp16.h>
#include <cstdint>

// Routed capsule layer, B200 (sm_100a).
// x[64,1152,8], W[64,1152,16,8] -> v[64,64,16], 3 routing iterations.
// b_t = (sum_{tau<=t} v_tau) . u  (logits linear in history); iter-1 c == 1/64.
// u cached in fp16, layout [b][i][o][k]. Routing math in HFMA2 (packed half2).

#define NB 64
#define NI 1152
#define KI 8
#define NO 64
#define KO 16

#define K1_IC 16
#define NCH1 (NI / K1_IC)   // 72 i-chunks for k_u partials
#define K2_IC 64
#define NCH2 (NI / K2_IC)   // 18 i-chunks for k_route partials

__device__ __half g_u[(size_t)NB * NI * NO * KO];        // 151 MB
// chunk-major partials: [chunk][b][o][k] -> coalesced writes AND reads
__device__ float g_sp[(size_t)NCH1 * NB * NO * KO];
__device__ float g_v1[NB * NO * KO];
__device__ float g_vsum[NB * NO * KO];

// dummy: shifts the fixed ncu capture window (-s 5 -c 1) onto k_route pass 3
__global__ void k_dummy() {}

// ---------------------------------------------------------------------------
// K1: u = W.x (fp16) + per-chunk partial sums (uniform-c first iteration).
// 8 warps (one o each); lane = ih*16 + k; W slice in registers (read once).
// Whole x tile (all 64 b) staged once; stores gathered through smem ->
// one STG.128 per thread per b. grid = (72 i-chunks, 8 o-chunks).
// ---------------------------------------------------------------------------
__global__ void __launch_bounds__(256, 2) k_u(const float* __restrict__ x,
                                              const float* __restrict__ W) {
    __shared__ float sX[NB * K1_IC * KI];            // 32 KB: [b][i_local][j]
    __shared__ __half sG[2][K1_IC * 8 * KO];         // 2 x 4 KB gather tiles

    const int ich = blockIdx.x, och = blockIdx.y;
    const int t = threadIdx.x;
    const int w = t >> 5;                   // local o
    const int l = t & 31;
    const int ih = l >> 4, k = l & 15;
    const int og = och * 8 + w;

    {   // stage x for ALL batches: 2048 float4, 8 per thread
        const float4* xs = (const float4*)(x + (size_t)ich * K1_IC * KI);
        float4* sx4 = (float4*)sX;
#pragma unroll
        for (int it = 0; it < 8; it++) {
            int idx = t + it * 256;
            int b = idx >> 5, r = idx & 31;
            sx4[idx] = xs[(size_t)b * (NI * KI / 4) + r];
        }
    }

    // register-resident W slice: 8 i x 8 j for this (og, k)
    float4 wr[16];
    {
        const float4* wp = (const float4*)(
            W + ((size_t)(og * NI + ich * K1_IC + ih * 8) * KO + k) * KI);
#pragma unroll
        for (int i = 0; i < 8; i++) {
            wr[2 * i]     = wp[i * 32];
            wr[2 * i + 1] = wp[i * 32 + 1];
        }
    }
    __syncthreads();

    const int grow = t >> 4;          // gather-store row (i_local 0..15)
    const int gcol = t & 15;          // gather-store col (16B unit)

    for (int b = 0; b < NB; b++) {
        __half* gb = sG[b & 1];
        float acc = 0.f;
        const float4* xb = (const float4*)(sX + b * (K1_IC * KI) + ih * 64);
#pragma unroll
        for (int i = 0; i < 8; i++) {
            const float4 x0 = xb[2 * i];
            const float4 x1 = xb[2 * i + 1];
            float v = wr[2*i].x   * x0.x + wr[2*i].y   * x0.y
                    + wr[2*i].z   * x0.z + wr[2*i].w   * x0.w
                    + wr[2*i+1].x * x1.x + wr[2*i+1].y * x1.y
                    + wr[2*i+1].z * x1.z + wr[2*i+1].w * x1.w;
            gb[(ih * 8 + i) * (8 * KO) + w * KO + k] = __float2half(v);
            acc += v;
        }
        acc += __shfl_xor_sync(0xffffffffu, acc, 16);   // join the two i-halves
        if (l < 16)   // chunk-major partial: [ich][b][og][k] (coalesced)
            g_sp[(size_t)(ich * NB + b) * (NO * KO) + og * KO + l] = acc;
        __syncthreads();   // gather tile complete
        uint4 val = ((const uint4*)gb)[t];
        ((uint4*)(g_u + (size_t)(b * NI + ich * K1_IC + grow) * (NO * KO)
                      + och * 128))[gcol] = val;
        // next iteration writes the other sG buffer: no barrier needed here
    }
}

// ---------------------------------------------------------------------------
// K2/K3: routing pass, HFMA2 math. Warp handles one (b,i) per iteration:
// lane l owns the kh=(l&1) half (8 k's = 4 half2) of o in {l>>1, 16+(l>>1),
// 32+(l>>1), 48+(l>>1)}: four coalesced uint4 loads per iter (2KB/warp),
// prefetch depth 2 (8 outstanding 128B loads/warp mid-compute).
// Logit dot and c*u accumulate run on packed half2 (HFMA2); the 8-i partial
// accumulator stays half2 and converts to fp32 once at the epilogue.
// grid = (18 i-chunks, 64 b), 256 threads (8 warps x 8 i each).
// ---------------------------------------------------------------------------
__global__ void __launch_bounds__(256, 2) k_route(int use_vsum) {
    const float* __restrict__ vin = use_vsum ? g_vsum : g_v1;
    __shared__ float sRed[8 * NO * KO];     // 32 KB per-warp partials

    const int ich = blockIdx.x, b = blockIdx.y;
    const int t = threadIdx.x, w = t >> 5, l = t & 31;
    const int o0 = l >> 1, kh = l & 1;

    // v slices for this lane's 4 capsules, packed half2 (k pairs)
    __half2 vp[4][4];
#pragma unroll
    for (int m = 0; m < 4; m++) {
        const float4* p = (const float4*)(vin + ((size_t)b * NO + (m * 16 + o0)) * KO + kh * 8);
        float4 a = p[0], c = p[1];
        vp[m][0] = __floats2half2_rn(a.x, a.y);
        vp[m][1] = __floats2half2_rn(a.z, a.w);
        vp[m][2] = __floats2half2_rn(c.x, c.y);
        vp[m][3] = __floats2half2_rn(c.z, c.w);
    }
    __half2 acch[4][4];
    const __half2 h2z = __float2half2_rn(0.f);
#pragma unroll
    for (int m = 0; m < 4; m++)
#pragma unroll
        for (int q = 0; q < 4; q++) acch[m][q] = h2z;

    // base for this warp's 8 i's; each i-row is 128 uint4
    const uint4* ub = (const uint4*)(g_u + (size_t)(b * NI + ich * K2_IC + w * 8) * (NO * KO));
    uint4 P0 = ub[l],       P1 = ub[l + 32],       P2 = ub[l + 64],       P3 = ub[l + 96];
    uint4 Q0 = ub[128 + l], Q1 = ub[128 + l + 32], Q2 = ub[128 + l + 64], Q3 = ub[128 + l + 96];

#pragma unroll
    for (int it = 0; it < 8; it++) {
        uint4 C0 = P0, C1 = P1, C2 = P2, C3 = P3;
        P0 = Q0; P1 = Q1; P2 = Q2; P3 = Q3;
        if (it < 6) {
            const uint4* un = ub + (it + 2) * 128;
            Q0 = un[l]; Q1 = un[l + 32]; Q2 = un[l + 64]; Q3 = un[l + 96];
        }
        const __half2* h0 = (const __half2*)&C0;
        const __half2* h1 = (const __half2*)&C1;
        const __half2* h2 = (const __half2*)&C2;
        const __half2* h3 = (const __half2*)&C3;

        // logits: packed half2 dot (4 HFMA2 each), horizontal in fp32
        __half2 d0 = __hmul2(h0[0], vp[0][0]);
        __half2 d1 = __hmul2(h1[0], vp[1][0]);
        __half2 d2 = __hmul2(h2[0], vp[2][0]);
        __half2 d3 = __hmul2(h3[0], vp[3][0]);
#pragma unroll
        for (int q = 1; q < 4; q++) {
            d0 = __hfma2(h0[q], vp[0][q], d0);
            d1 = __hfma2(h1[q], vp[1][q], d1);
            d2 = __hfma2(h2[q], vp[2][q], d2);
            d3 = __hfma2(h3[q], vp[3][q], d3);
        }
        float2 f0 = __half22float2(d0), f1 = __half22float2(d1);
        float2 f2 = __half22float2(d2), f3 = __half22float2(d3);
        float L0 = f0.x + f0.y, L1 = f1.x + f1.y;
        float L2 = f2.x + f2.y, L3 = f3.x + f3.y;
        L0 += __shfl_xor_sync(0xffffffffu, L0, 1);   // full 16-k dot
        L1 += __shfl_xor_sync(0xffffffffu, L1, 1);
        L2 += __shfl_xor_sync(0xffffffffu, L2, 1);
        L3 += __shfl_xor_sync(0xffffffffu, L3, 1);

        float mx = fmaxf(fmaxf(L0, L1), fmaxf(L2, L3));
#pragma unroll
        for (int d = 2; d <= 16; d <<= 1)
            mx = fmaxf(mx, __shfl_xor_sync(0xffffffffu, mx, d));
        float e0 = __expf(L0 - mx), e1 = __expf(L1 - mx);
        float e2 = __expf(L2 - mx), e3 = __expf(L3 - mx);
        float sm = (e0 + e1) + (e2 + e3);
#pragma unroll
        for (int d = 2; d <= 16; d <<= 1)
            sm += __shfl_xor_sync(0xffffffffu, sm, d);
        const float inv = __fdividef(1.f, sm);
        const __half2 c0 = __float2half2_rn(e0 * inv);
        const __half2 c1 = __float2half2_rn(e1 * inv);
        const __half2 c2 = __float2half2_rn(e2 * inv);
        const __half2 c3 = __float2half2_rn(e3 * inv);
#pragma unroll
        for (int q = 0; q < 4; q++) {
            acch[0][q] = __hfma2(h0[q], c0, acch[0][q]);
            acch[1][q] = __hfma2(h1[q], c1, acch[1][q]);
            acch[2][q] = __hfma2(h2[q], c2, acch[2][q]);
            acch[3][q] = __hfma2(h3[q], c3, acch[3][q]);
        }
    }

    // per-warp partials -> smem (fp32); element index for (m,lane): 256*m+8*l+q
    float4* sr4 = (float4*)sRed;
#pragma unroll
    for (int m = 0; m < 4; m++) {
        float2 a0 = __half22float2(acch[m][0]);
        float2 a1 = __half22float2(acch[m][1]);
        float2 a2 = __half22float2(acch[m][2]);
        float2 a3 = __half22float2(acch[m][3]);
        sr4[w * 256 + m * 64 + 2 * l]     = make_float4(a0.x, a0.y, a1.x, a1.y);
        sr4[w * 256 + m * 64 + 2 * l + 1] = make_float4(a2.x, a2.y, a3.x, a3.y);
    }
    __syncthreads();
    float4 r = sr4[t];
#pragma unroll
    for (int ww = 1; ww < 8; ww++) {
        float4 p = sr4[ww * 256 + t];
        r.x += p.x; r.y += p.y; r.z += p.z; r.w += p.w;
    }
    ((float4*)(g_sp + (size_t)(ich * NB + b) * (NO * KO)))[t] = r;   // coalesced
}

// ---------------------------------------------------------------------------
// Reduce chunk partials -> s, squash, write v. One thread per (b,o,k) element;
// chunk-major layout -> loads coalesced across threads at every chunk step.
// mode 0: v1 = squash(s/64); mode 1: vsum = v1 + squash(s); mode 2: out.
// ---------------------------------------------------------------------------
__global__ void __launch_bounds__(256) k_reduce(int nch, float scale, int mode,
                                                float* __restrict__ dout) {
    const int tg = blockIdx.x * 256 + threadIdx.x;   // b*1024 + o*16 + k
    const float* p = g_sp + tg;
    float s = 0.f;
#pragma unroll 6
    for (int c = 0; c < nch; c++) s += p[(size_t)c * (NB * NO * KO)];
    s *= scale;
    float n2 = s * s;
#pragma unroll
    for (int d = 1; d <= 8; d <<= 1)
        n2 += __shfl_xor_sync(0xffffffffu, n2, d);   // stays within k-group
    const float scl = n2 / (1.f + n2) * rsqrtf(n2 + 1e-7f);
    const float val = s * scl;
    if (mode == 0)      g_v1[tg] = val;
    else if (mode == 1) g_vsum[tg] = val + g_v1[tg];
    else                dout[tg] = val;
}

// ---------------------------------------------------------------------------
extern "C" void kernel_launch(void* const* d_in, const int* in_sizes, int n_in,
                              void* d_out, int out_size) {
    const float* x = (const float*)d_in[0];
    const float* W = (const float*)d_in[1];
    if (in_sizes[0] != NB * NI * KI) {
        x = (const float*)d_in[1];
        W = (const float*)d_in[0];
    }
    float* out = (float*)d_out;

    k_dummy<<<1, 1>>>();                                    // ncu window shim
    k_u<<<dim3(NCH1, NO / 8), 256>>>(x, W);                 // u + s1 partials
    k_reduce<<<256, 256>>>(NCH1, 1.f / 64.f, 0, nullptr);   // v1
    k_route<<<dim3(NCH2, NB), 256>>>(0);                    // s2
    k_reduce<<<256, 256>>>(NCH2, 1.f, 1, nullptr);          // v2, vsum
    k_route<<<dim3(NCH2, NB), 256>>>(1);                    // s3
    k_reduce<<<256, 256>>>(NCH2, 1.f, 2, out);              // v3 -> out
}

// round 10
// speedup vs baseline: 1.1669x; 1.0076x over previous
#include <cuda_runtime.h>
#include <cuda_fp16.h>
#include <cstdint>

// Routed capsule layer, B200 (sm_100a).
// x[64,1152,8], W[64,1152,16,8] -> v[64,64,16], 3 routing iterations.
// b_t = (sum_{tau<=t} v_tau) . u  (logits linear in history); iter-1 c == 1/64.
// u cached in fp16, layout [b][i][o][k]. Routing math in HFMA2 (packed half2).
// k_u math in packed f32x2 (FFMA2 via PTX - ptxas never auto-fuses).

#define NB 64
#define NI 1152
#define KI 8
#define NO 64
#define KO 16

#define K1_IC 16
#define NCH1 (NI / K1_IC)   // 72 i-chunks for k_u partials
#define K2_IC 64
#define NCH2 (NI / K2_IC)   // 18 i-chunks for k_route partials

__device__ __half g_u[(size_t)NB * NI * NO * KO];        // 151 MB
// chunk-major partials: [chunk][b][o][k] -> coalesced writes AND reads
__device__ float g_sp[(size_t)NCH1 * NB * NO * KO];
__device__ float g_v1[NB * NO * KO];
__device__ float g_vsum[NB * NO * KO];

// dummy: shifts the fixed ncu capture window (-s 5 -c 1) onto k_route pass 3
__global__ void k_dummy() {}

// ---------------------------------------------------------------------------
// packed fp32x2 helpers (sm_100a: one instruction = two fp32 FMA lanes)
// ---------------------------------------------------------------------------
__device__ __forceinline__ unsigned long long f2mul(unsigned long long a,
                                                    unsigned long long b) {
    unsigned long long r;
    asm("mul.rn.f32x2 %0, %1, %2;" : "=l"(r) : "l"(a), "l"(b));
    return r;
}
__device__ __forceinline__ unsigned long long f2fma(unsigned long long a,
                                                    unsigned long long b,
                                                    unsigned long long c) {
    unsigned long long r;
    asm("fma.rn.f32x2 %0, %1, %2, %3;" : "=l"(r) : "l"(a), "l"(b), "l"(c));
    return r;
}
__device__ __forceinline__ unsigned long long f2add(unsigned long long a,
                                                    unsigned long long b) {
    unsigned long long r;
    asm("add.rn.f32x2 %0, %1, %2;" : "=l"(r) : "l"(a), "l"(b));
    return r;
}
__device__ __forceinline__ float2 f2unpack(unsigned long long a) {
    float2 f;
    asm("mov.b64 {%0, %1}, %2;" : "=f"(f.x), "=f"(f.y) : "l"(a));
    return f;
}

// ---------------------------------------------------------------------------
// K1: u = W.x (fp16) + per-chunk partial sums (uniform-c first iteration).
// 8 warps (one o each); lane = ih*16 + k; W slice in registers (read once).
// Whole x tile (all 64 b) staged once; stores gathered through smem ->
// one STG.128 per thread per b. Inner dot runs on f32x2: mul2 + 3 fma2 per i
// (vs 8 scalar FFMA), packed chunk-partial accumulator, one horizontal add
// per stored u element. grid = (72 i-chunks, 8 o-chunks).
// ---------------------------------------------------------------------------
__global__ void __launch_bounds__(256, 2) k_u(const float* __restrict__ x,
                                              const float* __restrict__ W) {
    __shared__ float sX[NB * K1_IC * KI];            // 32 KB: [b][i_local][j]
    __shared__ __half sG[2][K1_IC * 8 * KO];         // 2 x 4 KB gather tiles

    const int ich = blockIdx.x, och = blockIdx.y;
    const int t = threadIdx.x;
    const int w = t >> 5;                   // local o
    const int l = t & 31;
    const int ih = l >> 4, k = l & 15;
    const int og = och * 8 + w;

    {   // stage x for ALL batches: 2048 float4, 8 per thread
        const float4* xs = (const float4*)(x + (size_t)ich * K1_IC * KI);
        float4* sx4 = (float4*)sX;
#pragma unroll
        for (int it = 0; it < 8; it++) {
            int idx = t + it * 256;
            int b = idx >> 5, r = idx & 31;
            sx4[idx] = xs[(size_t)b * (NI * KI / 4) + r];
        }
    }

    // register-resident W slice, packed as fp32 pairs: 8 i x 4 pairs
    ulonglong2 wr[16];
    {
        const ulonglong2* wp = (const ulonglong2*)(
            W + ((size_t)(og * NI + ich * K1_IC + ih * 8) * KO + k) * KI);
        // stride between consecutive i = KO*KI floats = 32 x 16B
#pragma unroll
        for (int i = 0; i < 8; i++) {
            wr[2 * i]     = wp[i * 32];
            wr[2 * i + 1] = wp[i * 32 + 1];
        }
    }
    __syncthreads();

    const int grow = t >> 4;          // gather-store row (i_local 0..15)
    const int gcol = t & 15;          // gather-store col (16B unit)

    for (int b = 0; b < NB; b++) {
        __half* gb = sG[b & 1];
        unsigned long long acc2 = 0ull;   // packed (0.f, 0.f)
        const ulonglong2* xb2 = (const ulonglong2*)(sX + b * (K1_IC * KI) + ih * 64);
#pragma unroll
        for (int i = 0; i < 8; i++) {
            const ulonglong2 xa = xb2[2 * i];
            const ulonglong2 xc = xb2[2 * i + 1];
            unsigned long long d = f2mul(wr[2 * i].x, xa.x);
            d = f2fma(wr[2 * i].y,     xa.y, d);
            d = f2fma(wr[2 * i + 1].x, xc.x, d);
            d = f2fma(wr[2 * i + 1].y, xc.y, d);
            acc2 = f2add(acc2, d);
            float2 dv = f2unpack(d);
            gb[(ih * 8 + i) * (8 * KO) + w * KO + k] = __float2half(dv.x + dv.y);
        }
        float2 av = f2unpack(acc2);
        float acc = av.x + av.y;
        acc += __shfl_xor_sync(0xffffffffu, acc, 16);   // join the two i-halves
        if (l < 16)   // chunk-major partial: [ich][b][og][k] (coalesced)
            g_sp[(size_t)(ich * NB + b) * (NO * KO) + og * KO + l] = acc;
        __syncthreads();   // gather tile complete
        uint4 val = ((const uint4*)gb)[t];
        ((uint4*)(g_u + (size_t)(b * NI + ich * K1_IC + grow) * (NO * KO)
                      + och * 128))[gcol] = val;
        // next iteration writes the other sG buffer: no barrier needed here
    }
}

// ---------------------------------------------------------------------------
// K2/K3: routing pass, HFMA2 math. Warp handles one (b,i) per iteration:
// lane l owns the kh=(l&1) half (8 k's = 4 half2) of o in {l>>1, 16+(l>>1),
// 32+(l>>1), 48+(l>>1)}: four coalesced uint4 loads per iter (2KB/warp),
// prefetch depth 2 (8 outstanding 128B loads/warp mid-compute).
// Logit dot and c*u accumulate run on packed half2 (HFMA2); the 8-i partial
// accumulator stays half2 and converts to fp32 once at the epilogue.
// grid = (18 i-chunks, 64 b), 256 threads (8 warps x 8 i each).
// ---------------------------------------------------------------------------
__global__ void __launch_bounds__(256, 2) k_route(int use_vsum) {
    const float* __restrict__ vin = use_vsum ? g_vsum : g_v1;
    __shared__ float sRed[8 * NO * KO];     // 32 KB per-warp partials

    const int ich = blockIdx.x, b = blockIdx.y;
    const int t = threadIdx.x, w = t >> 5, l = t & 31;
    const int o0 = l >> 1, kh = l & 1;

    // v slices for this lane's 4 capsules, packed half2 (k pairs)
    __half2 vp[4][4];
#pragma unroll
    for (int m = 0; m < 4; m++) {
        const float4* p = (const float4*)(vin + ((size_t)b * NO + (m * 16 + o0)) * KO + kh * 8);
        float4 a = p[0], c = p[1];
        vp[m][0] = __floats2half2_rn(a.x, a.y);
        vp[m][1] = __floats2half2_rn(a.z, a.w);
        vp[m][2] = __floats2half2_rn(c.x, c.y);
        vp[m][3] = __floats2half2_rn(c.z, c.w);
    }
    __half2 acch[4][4];
    const __half2 h2z = __float2half2_rn(0.f);
#pragma unroll
    for (int m = 0; m < 4; m++)
#pragma unroll
        for (int q = 0; q < 4; q++) acch[m][q] = h2z;

    // base for this warp's 8 i's; each i-row is 128 uint4
    const uint4* ub = (const uint4*)(g_u + (size_t)(b * NI + ich * K2_IC + w * 8) * (NO * KO));
    uint4 P0 = ub[l],       P1 = ub[l + 32],       P2 = ub[l + 64],       P3 = ub[l + 96];
    uint4 Q0 = ub[128 + l], Q1 = ub[128 + l + 32], Q2 = ub[128 + l + 64], Q3 = ub[128 + l + 96];

#pragma unroll
    for (int it = 0; it < 8; it++) {
        uint4 C0 = P0, C1 = P1, C2 = P2, C3 = P3;
        P0 = Q0; P1 = Q1; P2 = Q2; P3 = Q3;
        if (it < 6) {
            const uint4* un = ub + (it + 2) * 128;
            Q0 = un[l]; Q1 = un[l + 32]; Q2 = un[l + 64]; Q3 = un[l + 96];
        }
        const __half2* h0 = (const __half2*)&C0;
        const __half2* h1 = (const __half2*)&C1;
        const __half2* h2 = (const __half2*)&C2;
        const __half2* h3 = (const __half2*)&C3;

        // logits: packed half2 dot (4 HFMA2 each), horizontal in fp32
        __half2 d0 = __hmul2(h0[0], vp[0][0]);
        __half2 d1 = __hmul2(h1[0], vp[1][0]);
        __half2 d2 = __hmul2(h2[0], vp[2][0]);
        __half2 d3 = __hmul2(h3[0], vp[3][0]);
#pragma unroll
        for (int q = 1; q < 4; q++) {
            d0 = __hfma2(h0[q], vp[0][q], d0);
            d1 = __hfma2(h1[q], vp[1][q], d1);
            d2 = __hfma2(h2[q], vp[2][q], d2);
            d3 = __hfma2(h3[q], vp[3][q], d3);
        }
        float2 f0 = __half22float2(d0), f1 = __half22float2(d1);
        float2 f2 = __half22float2(d2), f3 = __half22float2(d3);
        float L0 = f0.x + f0.y, L1 = f1.x + f1.y;
        float L2 = f2.x + f2.y, L3 = f3.x + f3.y;
        L0 += __shfl_xor_sync(0xffffffffu, L0, 1);   // full 16-k dot
        L1 += __shfl_xor_sync(0xffffffffu, L1, 1);
        L2 += __shfl_xor_sync(0xffffffffu, L2, 1);
        L3 += __shfl_xor_sync(0xffffffffu, L3, 1);

        float mx = fmaxf(fmaxf(L0, L1), fmaxf(L2, L3));
#pragma unroll
        for (int d = 2; d <= 16; d <<= 1)
            mx = fmaxf(mx, __shfl_xor_sync(0xffffffffu, mx, d));
        float e0 = __expf(L0 - mx), e1 = __expf(L1 - mx);
        float e2 = __expf(L2 - mx), e3 = __expf(L3 - mx);
        float sm = (e0 + e1) + (e2 + e3);
#pragma unroll
        for (int d = 2; d <= 16; d <<= 1)
            sm += __shfl_xor_sync(0xffffffffu, sm, d);
        const float inv = __fdividef(1.f, sm);
        const __half2 c0 = __float2half2_rn(e0 * inv);
        const __half2 c1 = __float2half2_rn(e1 * inv);
        const __half2 c2 = __float2half2_rn(e2 * inv);
        const __half2 c3 = __float2half2_rn(e3 * inv);
#pragma unroll
        for (int q = 0; q < 4; q++) {
            acch[0][q] = __hfma2(h0[q], c0, acch[0][q]);
            acch[1][q] = __hfma2(h1[q], c1, acch[1][q]);
            acch[2][q] = __hfma2(h2[q], c2, acch[2][q]);
            acch[3][q] = __hfma2(h3[q], c3, acch[3][q]);
        }
    }

    // per-warp partials -> smem (fp32); element index for (m,lane): 256*m+8*l+q
    float4* sr4 = (float4*)sRed;
#pragma unroll
    for (int m = 0; m < 4; m++) {
        float2 a0 = __half22float2(acch[m][0]);
        float2 a1 = __half22float2(acch[m][1]);
        float2 a2 = __half22float2(acch[m][2]);
        float2 a3 = __half22float2(acch[m][3]);
        sr4[w * 256 + m * 64 + 2 * l]     = make_float4(a0.x, a0.y, a1.x, a1.y);
        sr4[w * 256 + m * 64 + 2 * l + 1] = make_float4(a2.x, a2.y, a3.x, a3.y);
    }
    __syncthreads();
    float4 r = sr4[t];
#pragma unroll
    for (int ww = 1; ww < 8; ww++) {
        float4 p = sr4[ww * 256 + t];
        r.x += p.x; r.y += p.y; r.z += p.z; r.w += p.w;
    }
    ((float4*)(g_sp + (size_t)(ich * NB + b) * (NO * KO)))[t] = r;   // coalesced
}

// ---------------------------------------------------------------------------
// Reduce chunk partials -> s, squash, write v. One thread per (b,o,k) element;
// chunk-major layout -> loads coalesced across threads at every chunk step.
// mode 0: v1 = squash(s/64); mode 1: vsum = v1 + squash(s); mode 2: out.
// ---------------------------------------------------------------------------
__global__ void __launch_bounds__(256) k_reduce(int nch, float scale, int mode,
                                                float* __restrict__ dout) {
    const int tg = blockIdx.x * 256 + threadIdx.x;   // b*1024 + o*16 + k
    const float* p = g_sp + tg;
    float s = 0.f;
#pragma unroll 6
    for (int c = 0; c < nch; c++) s += p[(size_t)c * (NB * NO * KO)];
    s *= scale;
    float n2 = s * s;
#pragma unroll
    for (int d = 1; d <= 8; d <<= 1)
        n2 += __shfl_xor_sync(0xffffffffu, n2, d);   // stays within k-group
    const float scl = n2 / (1.f + n2) * rsqrtf(n2 + 1e-7f);
    const float val = s * scl;
    if (mode == 0)      g_v1[tg] = val;
    else if (mode == 1) g_vsum[tg] = val + g_v1[tg];
    else                dout[tg] = val;
}

// ---------------------------------------------------------------------------
extern "C" void kernel_launch(void* const* d_in, const int* in_sizes, int n_in,
                              void* d_out, int out_size) {
    const float* x = (const float*)d_in[0];
    const float* W = (const float*)d_in[1];
    if (in_sizes[0] != NB * NI * KI) {
        x = (const float*)d_in[1];
        W = (const float*)d_in[0];
    }
    float* out = (float*)d_out;

    k_dummy<<<1, 1>>>();                                    // ncu window shim
    k_u<<<dim3(NCH1, NO / 8), 256>>>(x, W);                 // u + s1 partials
    k_reduce<<<256, 256>>>(NCH1, 1.f / 64.f, 0, nullptr);   // v1
    k_route<<<dim3(NCH2, NB), 256>>>(0);                    // s2
    k_reduce<<<256, 256>>>(NCH2, 1.f, 1, nullptr);          // v2, vsum
    k_route<<<dim3(NCH2, NB), 256>>>(1);                    // s3
    k_reduce<<<256, 256>>>(NCH2, 1.f, 2, out);              // v3 -> out
}